// round 15
// baseline (speedup 1.0000x reference)
#include <cuda_runtime.h>
#include <cuda_bf16.h>
#include <cstdint>

// EdgeConv fused, round 15: TP=64 tiles -> 72.3 KB smem -> 3 CTAs/SM (24 warps)
// for latency hiding. Gather/GEMM math identical to round 10/14.
// out[p][o] = sum_cc E[p][cc] * Wt[cc][o] + bias[o]
//   E = [gsum | x], Wt[cc<64] = W[o][cc]/20, Wt[cc>=64] = W[o][cc]-W[o][cc-64]

#define BB 4
#define NN 32768
#define KK 20
#define CC 64
#define C2 128
#define OUTD 64
#define TP 64
#define THREADS 256
#define ROWB 256        // A/W image row bytes; swizzle k' = (k&8)|((k^row)&7)

// smem byte offsets (main kernel)
#define OFF_W_HI  0               // 16 KB
#define OFF_W_LO  16384           // 16 KB
#define OFF_A_HI  32768           // 64*256 = 16 KB
#define OFF_A_LO  49152           // 16 KB
#define OFF_SCR   65536           // 8 warps x 256 floats = 8 KB
#define OFF_BIAS  73728
#define SMEM_BYTES (OFF_BIAS + 256)   // 73984 -> 3 CTAs/SM

#define XV_BLOCKS ((BB * NN) / 64)    // 2048

__device__ float g_xv[(size_t)BB * NN * 20];               // variant table 10.5 MB
__device__ __align__(16) unsigned short g_Whi[OUTD * C2];  // swizzled W images
__device__ __align__(16) unsigned short g_Wlo[OUTD * C2];

// ---------------- helpers ----------------
__device__ __forceinline__ unsigned smem_u32(const void* p) {
    unsigned a;
    asm("{ .reg .u64 t; cvta.to.shared.u64 t, %1; cvt.u32.u64 %0, t; }" : "=r"(a) : "l"(p));
    return a;
}
__device__ __forceinline__ void ldsm4(unsigned* r, unsigned addr) {
    asm volatile("ldmatrix.sync.aligned.m8n8.x4.shared.b16 {%0,%1,%2,%3}, [%4];"
                 : "=r"(r[0]), "=r"(r[1]), "=r"(r[2]), "=r"(r[3]) : "r"(addr));
}
__device__ __forceinline__ void mma16816(float* d, const unsigned* a,
                                         unsigned b0, unsigned b1) {
    asm volatile(
        "mma.sync.aligned.m16n8k16.row.col.f32.bf16.bf16.f32 "
        "{%0,%1,%2,%3}, {%4,%5,%6,%7}, {%8,%9}, {%0,%1,%2,%3};"
        : "+f"(d[0]), "+f"(d[1]), "+f"(d[2]), "+f"(d[3])
        : "r"(a[0]), "r"(a[1]), "r"(a[2]), "r"(a[3]), "r"(b0), "r"(b1));
}
__device__ __forceinline__ unsigned pack_hi(float a, float b, float& ra, float& rb) {
    __nv_bfloat16 ha = __float2bfloat16(a), hb = __float2bfloat16(b);
    ra = a - __bfloat162float(ha);
    rb = b - __bfloat162float(hb);
    return ((unsigned)__bfloat16_as_ushort(hb) << 16) | (unsigned)__bfloat16_as_ushort(ha);
}
__device__ __forceinline__ unsigned pack_lo(float ra, float rb) {
    __nv_bfloat16 la = __float2bfloat16(ra);
    __nv_bfloat16 lb = __float2bfloat16(rb);
    return ((unsigned)__bfloat16_as_ushort(lb) << 16) | (unsigned)__bfloat16_as_ushort(la);
}
__device__ __forceinline__ unsigned swz(int r, int k) {
    return (unsigned)(r * ROWB + (((k & 8) | ((k ^ r) & 7)) << 4));
}

// ---------------- merged prep: xv table (blocks < XV_BLOCKS) + W images ------
__global__ __launch_bounds__(256)
void edgeconv_prep_kernel(const float* __restrict__ x, const float* __restrict__ W)
{
    const int tid = threadIdx.x;

    if (blockIdx.x >= XV_BLOCKS) {
        int i = (blockIdx.x - XV_BLOCKS) * 256 + tid;
        if (i < OUTD * C2) {
            int o = i >> 7, cc = i & 127;
            float w = W[o * C2 + cc];
            if (cc < CC) w *= (1.0f / (float)KK);
            else         w -= W[o * C2 + (cc - CC)];
            __nv_bfloat16 h = __float2bfloat16(w);
            __nv_bfloat16 l = __float2bfloat16(w - __bfloat162float(h));
            unsigned byteoff = swz(o, cc >> 3) + ((cc & 7) << 1);
            g_Whi[byteoff >> 1] = __bfloat16_as_ushort(h);
            g_Wlo[byteoff >> 1] = __bfloat16_as_ushort(l);
        }
        return;
    }

    __shared__ float s4[64 * 16];
    const int R0 = blockIdx.x * 64;

    const float4* __restrict__ x4 = (const float4*)x + (size_t)R0 * 16;
    #pragma unroll
    for (int i = 0; i < 4; ++i) {
        int idx = tid + 256 * i;
        float4 v = x4[idx];
        s4[idx] = (v.x + v.y) + (v.z + v.w);
    }
    __syncthreads();

    #pragma unroll
    for (int pass = 0; pass < 2; ++pass) {
        int item = tid + pass * 256;
        if (item < 320) {
            int r = item / 5;
            int v = item - 5 * r;
            const float* s = &s4[r * 16];

            float ox = s[0];
            if (v < 4) ox += s[1];
            if (v < 3) ox += s[2];
            if (v < 2) ox += s[3];
            if (v < 1) ox += s[4];

            float ow = s[15];
            if (v > 0) ow += s[14];
            if (v > 1) ow += s[13];
            if (v > 2) ow += s[12];
            if (v > 3) ow += s[11];

            const float* sy = s + (5 - v);
            float oy = ((sy[0] + sy[1]) + (sy[2] + sy[3])) + sy[4];
            const float* sz = s + (10 - v);
            float oz = ((sz[0] + sz[1]) + (sz[2] + sz[3])) + sz[4];

            float4 o;
            o.x = ox; o.y = oy; o.z = oz; o.w = ow;
            *(float4*)&g_xv[(size_t)(R0 + r) * 20 + 4 * v] = o;
        }
    }
}

// ---------------- main fused kernel ----------------
__global__ __launch_bounds__(THREADS, 3)
void edgeconv_fused_kernel(const float* __restrict__ x,
                           const int* __restrict__ adj,
                           const float* __restrict__ bias,
                           float* __restrict__ out)
{
    extern __shared__ __align__(16) char smem[];
    const unsigned smem_base = smem_u32(smem);

    const int tid = threadIdx.x;
    const int wid = tid >> 5;
    const int lid = tid & 31;
    const int gp0 = blockIdx.x * TP;
    const int b   = gp0 >> 15;
    const int n0  = gp0 & (NN - 1);

    // ---- copy prepped W images + bias; zero scatter planes ----
    {
        const uint4* sh = (const uint4*)g_Whi;
        const uint4* sl = (const uint4*)g_Wlo;
        uint4* dh = (uint4*)(smem + OFF_W_HI);
        uint4* dl = (uint4*)(smem + OFF_W_LO);
        #pragma unroll
        for (int i = tid; i < (OUTD * C2) / 8; i += THREADS) { dh[i] = sh[i]; dl[i] = sl[i]; }
    }
    if (tid < OUTD) ((float*)(smem + OFF_BIAS))[tid] = bias[tid];

    float* __restrict__ sw = (float*)(smem + OFF_SCR) + wid * 256;
    #pragma unroll
    for (int i = lid; i < 256; i += 32) sw[i] = 0.0f;   // plane B stays 0 where unused
    __syncwarp();

    // ---- gather: warp owns points [8*wid, 8*wid+8), processed in pairs ----
    const float4* __restrict__ xv4 = (const float4*)g_xv + (size_t)b * NN * 5;
    const float2* __restrict__ xb2 = (const float2*)(x + (size_t)b * NN * CC);

    const bool act = (lid < KK);
    const int  vS  = act ? (lid % 5) : 0;
    const int  c0  = act ? ((16 * lid - vS) / 5) : 0;     // first window of slot
    const int  a3  = ((vS == 4) ? 0 : 64) + c0 + 3;       // k=3 target (A or B plane)

    int a[8];
    #pragma unroll
    for (int pi = 0; pi < 8; ++pi) {
        int gp = gp0 + 8 * wid + pi;
        a[pi] = act ? adj[(size_t)gp * KK + lid] : 0;
    }

    // prime the pipeline with pair 0
    float4 f0 = make_float4(0.f, 0.f, 0.f, 0.f);
    float4 f1 = make_float4(0.f, 0.f, 0.f, 0.f);
    if (act) {
        f0 = xv4[(size_t)a[0] * 5 + vS];
        f1 = xv4[(size_t)a[1] * 5 + vS];
    }
    float2 xc0 = xb2[(size_t)(n0 + 8 * wid + 0) * 32 + lid];
    float2 xc1 = xb2[(size_t)(n0 + 8 * wid + 1) * 32 + lid];

    #pragma unroll 1
    for (int pi = 0; pi < 8; pi += 2) {
        const int p = 8 * wid + pi;
        float* buf0 = sw;
        float* buf1 = sw + 128;

        if (act) {
            buf0[c0]     = f0.x;
            buf0[c0 + 1] = f0.y;
            buf0[c0 + 2] = f0.z;
            buf0[a3]     = f0.w;
            buf1[c0]     = f1.x;
            buf1[c0 + 1] = f1.y;
            buf1[c0 + 2] = f1.z;
            buf1[a3]     = f1.w;
        }

        // prefetch next pair (4 scattered LDGs in flight)
        float4 fn0 = make_float4(0.f, 0.f, 0.f, 0.f);
        float4 fn1 = make_float4(0.f, 0.f, 0.f, 0.f);
        float2 xn0 = make_float2(0.f, 0.f);
        float2 xn1 = make_float2(0.f, 0.f);
        if (pi < 6) {
            if (act) {
                fn0 = xv4[(size_t)a[pi + 2] * 5 + vS];
                fn1 = xv4[(size_t)a[pi + 3] * 5 + vS];
            }
            xn0 = xb2[(size_t)(n0 + p + 2) * 32 + lid];
            xn1 = xb2[(size_t)(n0 + p + 3) * 32 + lid];
        }

        __syncwarp();

        float2 ga0 = *(const float2*)&buf0[2 * lid];
        float2 gb0 = *(const float2*)&buf0[64 + 2 * lid];
        float2 ga1 = *(const float2*)&buf1[2 * lid];
        float2 gb1 = *(const float2*)&buf1[64 + 2 * lid];
        float wA0 = ga0.x + gb0.x, wB0 = ga0.y + gb0.y;
        float wA1 = ga1.x + gb1.x, wB1 = ga1.y + gb1.y;

        {
            float rg0, rg1, rx0, rx1;
            unsigned hp_g = pack_hi(wA0, wB0, rg0, rg1);
            unsigned hp_x = pack_hi(xc0.x, xc0.y, rx0, rx1);
            unsigned lp_g = pack_lo(rg0, rg1);
            unsigned lp_x = pack_lo(rx0, rx1);
            const int w4 = (lid & 3) << 2;
            unsigned offg = swz(p, lid >> 2)       + w4;
            unsigned offx = swz(p, 8 + (lid >> 2)) + w4;
            *(unsigned*)(smem + OFF_A_HI + offg) = hp_g;
            *(unsigned*)(smem + OFF_A_LO + offg) = lp_g;
            *(unsigned*)(smem + OFF_A_HI + offx) = hp_x;
            *(unsigned*)(smem + OFF_A_LO + offx) = lp_x;
        }
        {
            float rg0, rg1, rx0, rx1;
            unsigned hp_g = pack_hi(wA1, wB1, rg0, rg1);
            unsigned hp_x = pack_hi(xc1.x, xc1.y, rx0, rx1);
            unsigned lp_g = pack_lo(rg0, rg1);
            unsigned lp_x = pack_lo(rx0, rx1);
            const int w4 = (lid & 3) << 2;
            unsigned offg = swz(p + 1, lid >> 2)       + w4;
            unsigned offx = swz(p + 1, 8 + (lid >> 2)) + w4;
            *(unsigned*)(smem + OFF_A_HI + offg) = hp_g;
            *(unsigned*)(smem + OFF_A_LO + offg) = lp_g;
            *(unsigned*)(smem + OFF_A_HI + offx) = hp_x;
            *(unsigned*)(smem + OFF_A_LO + offx) = lp_x;
        }

        __syncwarp();   // WAR: planes reused next iteration

        f0 = fn0; f1 = fn1; xc0 = xn0; xc1 = xn1;
    }

    __syncthreads();

    // ---- GEMM: warps 2M x 4N, warp tile 32x16, K=128, bf16 3-product split ----
    const int mg = wid & 1;             // row group: 32*mg
    const int ng = wid >> 1;            // col group: 16*ng
    const int lrow  = (lid & 7) + 8 * ((lid >> 3) & 1);
    const int khalf = lid >> 4;

    const int rA0 = 32 * mg + lrow;
    const int rB0 = 16 * ng + (lid & 15);

    float d[2][2][4];
    #pragma unroll
    for (int mt = 0; mt < 2; ++mt)
        #pragma unroll
        for (int nt = 0; nt < 2; ++nt)
            #pragma unroll
            for (int e = 0; e < 4; ++e) d[mt][nt][e] = 0.0f;

    #pragma unroll 2
    for (int ks = 0; ks < 8; ++ks) {
        const int k = 2 * ks + khalf;
        const unsigned a0 = smem_base + OFF_A_HI + swz(rA0, k);
        const unsigned a1 = smem_base + OFF_A_HI + swz(rA0 + 16, k);
        const unsigned b0 = smem_base + OFF_W_HI + swz(rB0, k);

        unsigned ah[2][4], al[2][4];
        ldsm4(ah[0], a0);
        ldsm4(ah[1], a1);
        ldsm4(al[0], a0 + (OFF_A_LO - OFF_A_HI));
        ldsm4(al[1], a1 + (OFF_A_LO - OFF_A_HI));

        unsigned bh[4], bl[4];
        ldsm4(bh, b0);
        ldsm4(bl, b0 + (OFF_W_LO - OFF_W_HI));

        unsigned bhf[2][2] = {{bh[0], bh[2]}, {bh[1], bh[3]}};
        unsigned blf[2][2] = {{bl[0], bl[2]}, {bl[1], bl[3]}};

        #pragma unroll
        for (int mt = 0; mt < 2; ++mt) {
            #pragma unroll
            for (int nt = 0; nt < 2; ++nt) {
                mma16816(d[mt][nt], ah[mt], bhf[nt][0], bhf[nt][1]);
                mma16816(d[mt][nt], al[mt], bhf[nt][0], bhf[nt][1]);
                mma16816(d[mt][nt], ah[mt], blf[nt][0], blf[nt][1]);
            }
        }
    }

    // ---- epilogue: bias + direct store ----
    const float* sBias = (const float*)(smem + OFF_BIAS);
    const int g  = lid >> 2;
    const int oc = 2 * (lid & 3);
    #pragma unroll
    for (int mt = 0; mt < 2; ++mt) {
        const int prow = gp0 + 32 * mg + 16 * mt + g;
        #pragma unroll
        for (int nt = 0; nt < 2; ++nt) {
            const int o = 16 * ng + 8 * nt + oc;
            float2 bb = *(const float2*)&sBias[o];
            float2 r0, r1;
            r0.x = d[mt][nt][0] + bb.x;  r0.y = d[mt][nt][1] + bb.y;
            r1.x = d[mt][nt][2] + bb.x;  r1.y = d[mt][nt][3] + bb.y;
            *(float2*)&out[(size_t)prow * OUTD + o]       = r0;
            *(float2*)&out[(size_t)(prow + 8) * OUTD + o] = r1;
        }
    }
}

extern "C" void kernel_launch(void* const* d_in, const int* in_sizes, int n_in,
                              void* d_out, int out_size)
{
    (void)in_sizes; (void)n_in; (void)out_size;
    const float* x    = (const float*)d_in[0];
    const int*   adj  = (const int*)d_in[1];
    const float* W    = (const float*)d_in[2];
    const float* bias = (const float*)d_in[3];
    float* out = (float*)d_out;

    cudaFuncSetAttribute(edgeconv_fused_kernel,
                         cudaFuncAttributeMaxDynamicSharedMemorySize, SMEM_BYTES);

    edgeconv_prep_kernel<<<XV_BLOCKS + 32, 256>>>(x, W);
    const int tiles = (BB * NN) / TP;   // 2048
    edgeconv_fused_kernel<<<tiles, THREADS, SMEM_BYTES>>>(x, adj, bias, out);
}

// round 16
// speedup vs baseline: 1.0321x; 1.0321x over previous
#include <cuda_runtime.h>
#include <cuda_bf16.h>
#include <cstdint>

// EdgeConv fused, round 16: piece-level GEMM. Window assembly moved into the
// MMA accumulator via Wsub row-gather; gather loop is branch-free (1 LDG.128 +
// 2 STS.64 per slot-lane, no syncwarp, no scratch).
// out[p][o] = sum_{j,k} piece[p][4j+k]*Wsub[4j+k][o] + sum_c x[p][c]*Wx[c][o] + b[o]
//   Wsub[4j+k][o] = W[o][c0(j)+k]/20,  c0(j) = (16j - j%5)/5
//   Wx[c][o]      = W[o][64+c] - W[o][c]

#define BB 4
#define NN 32768
#define KK 20
#define CC 64
#define C2 128
#define OUTD 64
#define TP 64
#define THREADS 256

// smem byte offsets
#define OFF_WS_HI 0               // 64 x 160B  Wsub hi
#define OFF_WS_LO 10240
#define OFF_WX_HI 20480           // 64 x 128B  Wx hi
#define OFF_WX_LO 28672
#define OFF_AS_HI 36864           // 64 x 160B  pieces hi
#define OFF_AS_LO 47104
#define OFF_AX_HI 57344           // 64 x 128B  x hi
#define OFF_AX_LO 65536
#define OFF_BIAS  73728
#define SMEM_BYTES (OFF_BIAS + 256)   // 73984 -> 3 CTAs/SM

#define XV_BLOCKS ((BB * NN) / 64)    // 2048
#define W_ITEMS   (OUTD * 144)        // 9216 -> 36 blocks

__device__ uint4 g_xvu[(size_t)BB * NN * 5];           // packed hi/lo pieces 10.5 MB
__device__ __align__(16) unsigned char g_WsHi[OUTD * 160];
__device__ __align__(16) unsigned char g_WsLo[OUTD * 160];
__device__ __align__(16) unsigned char g_WxHi[OUTD * 128];
__device__ __align__(16) unsigned char g_WxLo[OUTD * 128];

// ---------------- helpers ----------------
__device__ __forceinline__ unsigned smem_u32(const void* p) {
    unsigned a;
    asm("{ .reg .u64 t; cvta.to.shared.u64 t, %1; cvt.u32.u64 %0, t; }" : "=r"(a) : "l"(p));
    return a;
}
__device__ __forceinline__ void ldsm4(unsigned* r, unsigned addr) {
    asm volatile("ldmatrix.sync.aligned.m8n8.x4.shared.b16 {%0,%1,%2,%3}, [%4];"
                 : "=r"(r[0]), "=r"(r[1]), "=r"(r[2]), "=r"(r[3]) : "r"(addr));
}
__device__ __forceinline__ void mma16816(float* d, const unsigned* a,
                                         unsigned b0, unsigned b1) {
    asm volatile(
        "mma.sync.aligned.m16n8k16.row.col.f32.bf16.bf16.f32 "
        "{%0,%1,%2,%3}, {%4,%5,%6,%7}, {%8,%9}, {%0,%1,%2,%3};"
        : "+f"(d[0]), "+f"(d[1]), "+f"(d[2]), "+f"(d[3])
        : "r"(a[0]), "r"(a[1]), "r"(a[2]), "r"(a[3]), "r"(b0), "r"(b1));
}
__device__ __forceinline__ unsigned pack_hi(float a, float b, float& ra, float& rb) {
    __nv_bfloat16 ha = __float2bfloat16(a), hb = __float2bfloat16(b);
    ra = a - __bfloat162float(ha);
    rb = b - __bfloat162float(hb);
    return ((unsigned)__bfloat16_as_ushort(hb) << 16) | (unsigned)__bfloat16_as_ushort(ha);
}
__device__ __forceinline__ unsigned pack_lo(float ra, float rb) {
    __nv_bfloat16 la = __float2bfloat16(ra);
    __nv_bfloat16 lb = __float2bfloat16(rb);
    return ((unsigned)__bfloat16_as_ushort(lb) << 16) | (unsigned)__bfloat16_as_ushort(la);
}
// 160B-row images: 10 chunks; XOR-swizzle chunks 0-7, passthrough 8-9
__device__ __forceinline__ unsigned swzS(int r, int k) {
    int ks = (k < 8) ? ((k ^ r) & 7) : k;
    return (unsigned)(r * 160 + ks * 16);
}
// 128B-row images: 8 chunks, full XOR swizzle
__device__ __forceinline__ unsigned swzX(int r, int k) {
    return (unsigned)(r * 128 + (((k ^ r) & 7) << 4));
}

// ---------------- prep: xv pieces (packed bf16 hi/lo) + weight images --------
__global__ __launch_bounds__(256)
void edgeconv_prep_kernel(const float* __restrict__ x, const float* __restrict__ W)
{
    const int tid = threadIdx.x;

    if (blockIdx.x >= XV_BLOCKS) {
        int i = (blockIdx.x - XV_BLOCKS) * 256 + tid;
        if (i < W_ITEMS) {
            int o = i / 144;
            int t = i - 144 * o;
            if (t < 80) {
                int j = t >> 2, k = t & 3;
                int v = j % 5;
                int c = (16 * j - v) / 5 + k;
                float w = W[o * C2 + c] * (1.0f / (float)KK);
                __nv_bfloat16 h = __float2bfloat16(w);
                __nv_bfloat16 l = __float2bfloat16(w - __bfloat162float(h));
                unsigned off = swzS(o, t >> 3) + ((t & 7) << 1);
                *(unsigned short*)(g_WsHi + off) = __bfloat16_as_ushort(h);
                *(unsigned short*)(g_WsLo + off) = __bfloat16_as_ushort(l);
            } else {
                int cx = t - 80;
                float w = W[o * C2 + 64 + cx] - W[o * C2 + cx];
                __nv_bfloat16 h = __float2bfloat16(w);
                __nv_bfloat16 l = __float2bfloat16(w - __bfloat162float(h));
                unsigned off = swzX(o, cx >> 3) + ((cx & 7) << 1);
                *(unsigned short*)(g_WxHi + off) = __bfloat16_as_ushort(h);
                *(unsigned short*)(g_WxLo + off) = __bfloat16_as_ushort(l);
            }
        }
        return;
    }

    __shared__ float s4[64 * 16];
    const int R0 = blockIdx.x * 64;

    const float4* __restrict__ x4 = (const float4*)x + (size_t)R0 * 16;
    #pragma unroll
    for (int i = 0; i < 4; ++i) {
        int idx = tid + 256 * i;
        float4 v = x4[idx];
        s4[idx] = (v.x + v.y) + (v.z + v.w);
    }
    __syncthreads();

    #pragma unroll
    for (int pass = 0; pass < 2; ++pass) {
        int item = tid + pass * 256;
        if (item < 320) {
            int r = item / 5;
            int v = item - 5 * r;
            const float* s = &s4[r * 16];

            float ox = s[0];
            if (v < 4) ox += s[1];
            if (v < 3) ox += s[2];
            if (v < 2) ox += s[3];
            if (v < 1) ox += s[4];

            float ow = s[15];
            if (v > 0) ow += s[14];
            if (v > 1) ow += s[13];
            if (v > 2) ow += s[12];
            if (v > 3) ow += s[11];

            const float* sy = s + (5 - v);
            float oy = ((sy[0] + sy[1]) + (sy[2] + sy[3])) + sy[4];
            const float* sz = s + (10 - v);
            float oz = ((sz[0] + sz[1]) + (sz[2] + sz[3])) + sz[4];

            float r0, r1, r2, r3;
            unsigned hi01 = pack_hi(ox, oy, r0, r1);
            unsigned hi23 = pack_hi(oz, ow, r2, r3);
            unsigned lo01 = pack_lo(r0, r1);
            unsigned lo23 = pack_lo(r2, r3);
            uint4 u; u.x = hi01; u.y = hi23; u.z = lo01; u.w = lo23;
            g_xvu[(size_t)(R0 + r) * 5 + v] = u;
        }
    }
}

// ---------------- main fused kernel ----------------
__global__ __launch_bounds__(THREADS, 3)
void edgeconv_fused_kernel(const float* __restrict__ x,
                           const int* __restrict__ adj,
                           const float* __restrict__ bias,
                           float* __restrict__ out)
{
    extern __shared__ __align__(16) char smem[];
    const unsigned smem_base = smem_u32(smem);

    const int tid = threadIdx.x;
    const int wid = tid >> 5;
    const int lid = tid & 31;
    const int gp0 = blockIdx.x * TP;
    const int b   = gp0 >> 15;
    const int n0  = gp0 & (NN - 1);

    // ---- copy prepped weight images (flat, already swizzled) + bias ----
    {
        const uint4* s0 = (const uint4*)g_WsHi;   // 640 uint4
        const uint4* s1 = (const uint4*)g_WsLo;   // 640
        uint4* d0 = (uint4*)(smem + OFF_WS_HI);
        uint4* d1 = (uint4*)(smem + OFF_WS_LO);
        #pragma unroll
        for (int i = tid; i < 640; i += THREADS) { d0[i] = s0[i]; d1[i] = s1[i]; }
        const uint4* s2 = (const uint4*)g_WxHi;   // 512
        const uint4* s3 = (const uint4*)g_WxLo;
        uint4* d2 = (uint4*)(smem + OFF_WX_HI);
        uint4* d3 = (uint4*)(smem + OFF_WX_LO);
        #pragma unroll
        for (int i = tid; i < 512; i += THREADS) { d2[i] = s2[i]; d3[i] = s3[i]; }
    }
    if (tid < OUTD) ((float*)(smem + OFF_BIAS))[tid] = bias[tid];

    // ---- gather: warp owns points [8*wid, 8*wid+8), branch-free ----
    const uint4* __restrict__ xvu = g_xvu + (size_t)b * NN * 5;
    const float2* __restrict__ xb2 = (const float2*)(x + (size_t)b * NN * CC);

    const bool act = (lid < KK);
    const int  vS  = act ? (lid % 5) : 0;
    const unsigned sofsK = ((lid & 1) << 3);   // 0/8 within chunk
    const int chS = lid >> 1;                  // slot chunk 0..9 (lanes 0-19)
    const int chX = lid >> 2;                  // x chunk 0..7
    const unsigned xofsK = ((lid & 3) << 2);

    int a[8];
    #pragma unroll
    for (int pi = 0; pi < 8; ++pi) {
        int gp = gp0 + 8 * wid + pi;
        a[pi] = act ? adj[(size_t)gp * KK + lid] : 0;
    }

    #pragma unroll
    for (int pi = 0; pi < 8; ++pi) {
        const int p = 8 * wid + pi;

        if (act) {
            uint4 u = xvu[(size_t)a[pi] * 5 + vS];
            unsigned off = swzS(p, chS) + sofsK;
            uint2 uh; uh.x = u.x; uh.y = u.y;
            uint2 ul; ul.x = u.z; ul.y = u.w;
            *(uint2*)(smem + OFF_AS_HI + off) = uh;
            *(uint2*)(smem + OFF_AS_LO + off) = ul;
        }

        float2 xc = xb2[(size_t)(n0 + p) * 32 + lid];
        float r0, r1;
        unsigned hp = pack_hi(xc.x, xc.y, r0, r1);
        unsigned lp = pack_lo(r0, r1);
        unsigned xoff = swzX(p, chX) + xofsK;
        *(unsigned*)(smem + OFF_AX_HI + xoff) = hp;
        *(unsigned*)(smem + OFF_AX_LO + xoff) = lp;
    }

    __syncthreads();

    // ---- GEMM: warps 2M x 4N, warp tile 32x16; K = 80 (pieces) + 64 (x) ----
    const int mg = wid & 1;
    const int ng = wid >> 1;
    const int lrow  = (lid & 7) + 8 * ((lid >> 3) & 1);
    const int khalf = lid >> 4;

    const int rA0 = 32 * mg + lrow;
    const int rB0 = 16 * ng + (lid & 15);

    float d[2][2][4];
    #pragma unroll
    for (int mt = 0; mt < 2; ++mt)
        #pragma unroll
        for (int nt = 0; nt < 2; ++nt)
            #pragma unroll
            for (int e = 0; e < 4; ++e) d[mt][nt][e] = 0.0f;

    // slot-piece part: K=80, 5 k-steps
    #pragma unroll
    for (int ks = 0; ks < 5; ++ks) {
        const int k = 2 * ks + khalf;
        const unsigned a0 = smem_base + OFF_AS_HI + swzS(rA0, k);
        const unsigned a1 = smem_base + OFF_AS_HI + swzS(rA0 + 16, k);
        const unsigned b0 = smem_base + OFF_WS_HI + swzS(rB0, k);

        unsigned ah[2][4], al[2][4];
        ldsm4(ah[0], a0);
        ldsm4(ah[1], a1);
        ldsm4(al[0], a0 + (OFF_AS_LO - OFF_AS_HI));
        ldsm4(al[1], a1 + (OFF_AS_LO - OFF_AS_HI));

        unsigned bh[4], bl[4];
        ldsm4(bh, b0);
        ldsm4(bl, b0 + (OFF_WS_LO - OFF_WS_HI));

        unsigned bhf[2][2] = {{bh[0], bh[2]}, {bh[1], bh[3]}};
        unsigned blf[2][2] = {{bl[0], bl[2]}, {bl[1], bl[3]}};

        #pragma unroll
        for (int mt = 0; mt < 2; ++mt)
            #pragma unroll
            for (int nt = 0; nt < 2; ++nt) {
                mma16816(d[mt][nt], ah[mt], bhf[nt][0], bhf[nt][1]);
                mma16816(d[mt][nt], al[mt], bhf[nt][0], bhf[nt][1]);
                mma16816(d[mt][nt], ah[mt], blf[nt][0], blf[nt][1]);
            }
    }

    // x part: K=64, 4 k-steps
    #pragma unroll
    for (int ks = 0; ks < 4; ++ks) {
        const int k = 2 * ks + khalf;
        const unsigned a0 = smem_base + OFF_AX_HI + swzX(rA0, k);
        const unsigned a1 = smem_base + OFF_AX_HI + swzX(rA0 + 16, k);
        const unsigned b0 = smem_base + OFF_WX_HI + swzX(rB0, k);

        unsigned ah[2][4], al[2][4];
        ldsm4(ah[0], a0);
        ldsm4(ah[1], a1);
        ldsm4(al[0], a0 + (OFF_AX_LO - OFF_AX_HI));
        ldsm4(al[1], a1 + (OFF_AX_LO - OFF_AX_HI));

        unsigned bh[4], bl[4];
        ldsm4(bh, b0);
        ldsm4(bl, b0 + (OFF_WX_LO - OFF_WX_HI));

        unsigned bhf[2][2] = {{bh[0], bh[2]}, {bh[1], bh[3]}};
        unsigned blf[2][2] = {{bl[0], bl[2]}, {bl[1], bl[3]}};

        #pragma unroll
        for (int mt = 0; mt < 2; ++mt)
            #pragma unroll
            for (int nt = 0; nt < 2; ++nt) {
                mma16816(d[mt][nt], ah[mt], bhf[nt][0], bhf[nt][1]);
                mma16816(d[mt][nt], al[mt], bhf[nt][0], bhf[nt][1]);
                mma16816(d[mt][nt], ah[mt], blf[nt][0], blf[nt][1]);
            }
    }

    // ---- epilogue: bias + direct store ----
    const float* sBias = (const float*)(smem + OFF_BIAS);
    const int g  = lid >> 2;
    const int oc = 2 * (lid & 3);
    #pragma unroll
    for (int mt = 0; mt < 2; ++mt) {
        const int prow = gp0 + 32 * mg + 16 * mt + g;
        #pragma unroll
        for (int nt = 0; nt < 2; ++nt) {
            const int o = 16 * ng + 8 * nt + oc;
            float2 bb = *(const float2*)&sBias[o];
            float2 r0, r1;
            r0.x = d[mt][nt][0] + bb.x;  r0.y = d[mt][nt][1] + bb.y;
            r1.x = d[mt][nt][2] + bb.x;  r1.y = d[mt][nt][3] + bb.y;
            *(float2*)&out[(size_t)prow * OUTD + o]       = r0;
            *(float2*)&out[(size_t)(prow + 8) * OUTD + o] = r1;
        }
    }
}

extern "C" void kernel_launch(void* const* d_in, const int* in_sizes, int n_in,
                              void* d_out, int out_size)
{
    (void)in_sizes; (void)n_in; (void)out_size;
    const float* x    = (const float*)d_in[0];
    const int*   adj  = (const int*)d_in[1];
    const float* W    = (const float*)d_in[2];
    const float* bias = (const float*)d_in[3];
    float* out = (float*)d_out;

    cudaFuncSetAttribute(edgeconv_fused_kernel,
                         cudaFuncAttributeMaxDynamicSharedMemorySize, SMEM_BYTES);

    edgeconv_prep_kernel<<<XV_BLOCKS + 36, 256>>>(x, W);
    const int tiles = (BB * NN) / TP;   // 2048
    edgeconv_fused_kernel<<<tiles, THREADS, SMEM_BYTES>>>(x, adj, bias, out);
}